// round 15
// baseline (speedup 1.0000x reference)
#include <cuda_runtime.h>

// ----------------------------------------------------------------------------
// PeriodicPrimitives2D — 3 pixels/thread (3 independent chains; ILP covers
// MUFU/LDS latency at the chronic ~30% occupancy), strided pixel assignment,
// __launch_bounds__(128,5) -> 5 blocks/SM, grid 739 = one uniform wave.
// Math identical to the 2441us best: packed-f32x2 exact phase reduction,
// MUFU cos / ex2 gaussian.
// ----------------------------------------------------------------------------

#define MAX_G 4096
#define TILE  256
#define BLK   128
#define PXT   3
#define PPB   355    // pixels per block (355*739 >= 262144, ~one wave at occ 5)

typedef unsigned long long u64;

// Per-gaussian packed data (written by prep kernel)
__device__ float4 dP [MAX_G];       // c, -s, s, c
__device__ float4 dQ [MAX_G];       // -ox, -oy, sx', sy'
__device__ float4 dC [MAX_G];       // col0, col1, col2, 0
__device__ float4 dFK[MAX_G * 4];   // fx_k, fy_k, cx_k, cy_k

// ---------------- f32x2 packed helpers --------------------------------------
__device__ __forceinline__ u64 pk2(float a, float b) {
    u64 r;
    asm("mov.b64 %0, {%1, %2};" : "=l"(r)
        : "r"(__float_as_uint(a)), "r"(__float_as_uint(b)));
    return r;
}
__device__ __forceinline__ void upk2(u64 v, float& a, float& b) {
    unsigned int lo, hi;
    asm("mov.b64 {%0, %1}, %2;" : "=r"(lo), "=r"(hi) : "l"(v));
    a = __uint_as_float(lo);
    b = __uint_as_float(hi);
}
__device__ __forceinline__ u64 mul2(u64 a, u64 b) {
    u64 r; asm("mul.rn.f32x2 %0, %1, %2;" : "=l"(r) : "l"(a), "l"(b)); return r;
}
__device__ __forceinline__ u64 fma2(u64 a, u64 b, u64 c) {
    u64 r; asm("fma.rn.f32x2 %0, %1, %2, %3;" : "=l"(r) : "l"(a), "l"(b), "l"(c));
    return r;
}
__device__ __forceinline__ float ex2(float x) {
    float r; asm("ex2.approx.f32 %0, %1;" : "=f"(r) : "f"(x)); return r;
}
__device__ __forceinline__ float cosap(float x) {
    float r; asm("cos.approx.f32 %0, %1;" : "=f"(r) : "f"(x)); return r;
}

// Packed constants
#define C2v   0x4B4000004B400000ULL  //  1.5 * 2^23 (round-to-int magic)
#define NEG1v 0xBF800000BF800000ULL  // -1.0f
#define PI2v  0x40C90FDB40C90FDBULL  //  2*pi

// ---------------- prep: fold per-gaussian transcendentals, repack -----------
__global__ void prep_kernel(const float* __restrict__ colors,
                            const float* __restrict__ pos,
                            const float* __restrict__ scales,
                            const float* __restrict__ rots,
                            const float* __restrict__ coeffs,
                            const int*   __restrict__ indices,
                            int G) {
    int g = blockIdx.x * blockDim.x + threadIdx.x;
    if (g >= G) return;
    float s, c;
    sincosf(rots[g], &s, &c);
    float gx = pos[2 * g], gy = pos[2 * g + 1];
    float ox =  gx * c + gy * s;
    float oy = -gx * s + gy * c;
    // s' = e^scale * sqrt(0.5 * log2(e)) :  exp(-0.5*(t e^s)^2) = 2^(-(t s')^2)
    const float SCL = 0.84932180625508979f;
    dP[g] = make_float4(c, -s, s, c);
    dQ[g] = make_float4(-ox, -oy, expf(scales[2 * g]) * SCL,
                                  expf(scales[2 * g + 1]) * SCL);
    dC[g] = make_float4(colors[3 * g], colors[3 * g + 1], colors[3 * g + 2], 0.0f);

    const float FS = 1024.0f / 1024.0f;  // max_frequency / num_frequencies
#pragma unroll
    for (int k = 0; k < 4; k++) {
        float fx = (float)indices[(g * 4 + k) * 2 + 0] * FS;
        float fy = (float)indices[(g * 4 + k) * 2 + 1] * FS;
        float cx = coeffs[(g * 4 + k) * 2 + 0];
        float cy = coeffs[(g * 4 + k) * 2 + 1];
        dFK[g * 4 + k] = make_float4(fx, fy, cx, cy);
    }
}

// ---------------- render: 3 px/thread (strided), smem gaussian tiles --------
__global__ __launch_bounds__(BLK, 5)
void render_kernel(const float* __restrict__ x, float* __restrict__ out,
                   int N, int G) {
    __shared__ float4 sP [TILE];
    __shared__ float4 sQ [TILE];
    __shared__ float4 sC [TILE];
    __shared__ float4 sFK[TILE * 4];

    int tid  = threadIdx.x;
    int base = blockIdx.x * PPB;
    int lim  = min(base + PPB, N);

    int   idx[PXT];
    u64   Px [PXT], Py[PXT];
    bool  ok [PXT];
#pragma unroll
    for (int q = 0; q < PXT; q++) {
        int i = base + q * BLK + tid;
        idx[q] = i;
        ok[q]  = (i < lim);
        float pxq = 0.f, pyq = 0.f;
        if (ok[q]) {
            float2 pp = reinterpret_cast<const float2*>(x)[i];
            pxq = pp.x; pyq = pp.y;
        }
        Px[q] = pk2(pxq, pxq);
        Py[q] = pk2(pyq, pyq);
    }

    float acc[PXT][3];
#pragma unroll
    for (int q = 0; q < PXT; q++) acc[q][0] = acc[q][1] = acc[q][2] = 0.f;

    const ulonglong2* pP  = reinterpret_cast<const ulonglong2*>(sP);
    const ulonglong2* pQ  = reinterpret_cast<const ulonglong2*>(sQ);
    const ulonglong2* pFK = reinterpret_cast<const ulonglong2*>(sFK);

    for (int t0 = 0; t0 < G; t0 += TILE) {
#pragma unroll
        for (int v = tid; v < TILE; v += BLK) {
            int gi = t0 + v;
            if (gi < G) {
                sP[v] = dP[gi];
                sQ[v] = dQ[gi];
                sC[v] = dC[gi];
#pragma unroll
                for (int k = 0; k < 4; k++) sFK[4 * v + k] = dFK[4 * gi + k];
            }
        }
        __syncthreads();

        int cnt = min(TILE, G - t0);
#pragma unroll 1
        for (int j = 0; j < cnt; j++) {
            ulonglong2 P = pP[j];            // (c,-s) , (s,c)
            ulonglong2 Q = pQ[j];            // (-ox,-oy) , (sx',sy')

            u64   t [PXT];
            float gw[PXT];
#pragma unroll
            for (int q = 0; q < PXT; q++) {
                u64 tq = fma2(Py[q], P.y, Q.x);
                tq = fma2(Px[q], P.x, tq);   // (tx, ty)
                t[q] = tq;
                u64 gq = mul2(tq, Q.y);
                float gx_, gy_; upk2(gq, gx_, gy_);
                gw[q] = ex2(fmaf(gx_, -gx_, gy_ * -gy_));
            }

            float wx[PXT], wy[PXT];
#pragma unroll
            for (int q = 0; q < PXT; q++) { wx[q] = 0.f; wy[q] = 0.f; }

#pragma unroll
            for (int k = 0; k < 4; k++) {
                ulonglong2 FK = pFK[4 * j + k];   // (fx,fy) , (cx,cy)
                float cx, cy; upk2(FK.y, cx, cy);
#pragma unroll
                for (int q = 0; q < PXT; q++) {
                    u64 s1 = fma2(t[q], FK.x, C2v);   // MAGIC + rint(t*f) (exact)
                    u64 rn = fma2(s1, NEG1v, C2v);    // -rint(t*f)        (exact)
                    u64 d  = fma2(t[q], FK.x, rn);    // t*f mod 1, centered
                    u64 ar = mul2(d, PI2v);
                    float x0, x1; upk2(ar, x0, x1);
                    wx[q] = fmaf(cosap(x0), cx, wx[q]);
                    wy[q] = fmaf(cosap(x1), cy, wy[q]);
                }
            }

            float4 C = sC[j];
#pragma unroll
            for (int q = 0; q < PXT; q++) {
                float w = gw[q] * wx[q] * wy[q];
                acc[q][0] = fmaf(w, C.x, acc[q][0]);
                acc[q][1] = fmaf(w, C.y, acc[q][1]);
                acc[q][2] = fmaf(w, C.z, acc[q][2]);
            }
        }
        __syncthreads();
    }

#pragma unroll
    for (int q = 0; q < PXT; q++) {
        if (ok[q]) {
            out[3 * idx[q] + 0] = acc[q][0];
            out[3 * idx[q] + 1] = acc[q][1];
            out[3 * idx[q] + 2] = acc[q][2];
        }
    }
}

// ---------------- harness entry ---------------------------------------------
extern "C" void kernel_launch(void* const* d_in, const int* in_sizes, int n_in,
                              void* d_out, int out_size) {
    const float* x       = (const float*)d_in[0];  // [N,2]
    const float* colors  = (const float*)d_in[1];  // [G,3]
    const float* pos     = (const float*)d_in[2];  // [G,2]
    const float* scales  = (const float*)d_in[3];  // [G,2]
    const float* rots    = (const float*)d_in[4];  // [G,1]
    const float* coeffs  = (const float*)d_in[5];  // [G,4,2]
    const int*   indices = (const int*)  d_in[6];  // [G,4,2]

    int N = in_sizes[0] / 2;
    int G = in_sizes[1] / 3;
    if (G > MAX_G) G = MAX_G;

    (void)cudaFuncSetAttribute(render_kernel,
                               cudaFuncAttributePreferredSharedMemoryCarveout,
                               cudaSharedmemCarveoutMaxShared);

    prep_kernel<<<(G + 255) / 256, 256>>>(colors, pos, scales, rots,
                                          coeffs, indices, G);

    int nBlocks = (N + PPB - 1) / PPB;    // 739 for N=262144
    render_kernel<<<nBlocks, BLK>>>(x, (float*)d_out, N, G);
}

// round 16
// speedup vs baseline: 1.1252x; 1.1252x over previous
#include <cuda_runtime.h>

// ----------------------------------------------------------------------------
// PeriodicPrimitives2D — R11 body (best: 2 pixels/thread, TILE=256, packed
// f32x2 exact phase reduction, MUFU cos/ex2, launch_bounds(128,7)+carveout)
// + constant inner trip count (zero-filled tail) + unroll 4.
// ----------------------------------------------------------------------------

#define MAX_G 4096
#define TILE  256
#define BLK   128     // threads per block; each thread owns 2 pixels

typedef unsigned long long u64;

// Per-gaussian packed data (written by prep kernel)
__device__ float4 dP [MAX_G];       // c, -s, s, c
__device__ float4 dQ [MAX_G];       // -ox, -oy, sx', sy'
__device__ float4 dC [MAX_G];       // col0, col1, col2, 0
__device__ float4 dFK[MAX_G * 4];   // fx_k, fy_k, cx_k, cy_k

// ---------------- f32x2 packed helpers --------------------------------------
__device__ __forceinline__ u64 pk2(float a, float b) {
    u64 r;
    asm("mov.b64 %0, {%1, %2};" : "=l"(r)
        : "r"(__float_as_uint(a)), "r"(__float_as_uint(b)));
    return r;
}
__device__ __forceinline__ void upk2(u64 v, float& a, float& b) {
    unsigned int lo, hi;
    asm("mov.b64 {%0, %1}, %2;" : "=r"(lo), "=r"(hi) : "l"(v));
    a = __uint_as_float(lo);
    b = __uint_as_float(hi);
}
__device__ __forceinline__ u64 mul2(u64 a, u64 b) {
    u64 r; asm("mul.rn.f32x2 %0, %1, %2;" : "=l"(r) : "l"(a), "l"(b)); return r;
}
__device__ __forceinline__ u64 fma2(u64 a, u64 b, u64 c) {
    u64 r; asm("fma.rn.f32x2 %0, %1, %2, %3;" : "=l"(r) : "l"(a), "l"(b), "l"(c));
    return r;
}
__device__ __forceinline__ float ex2(float x) {
    float r; asm("ex2.approx.f32 %0, %1;" : "=f"(r) : "f"(x)); return r;
}
__device__ __forceinline__ float cosap(float x) {
    float r; asm("cos.approx.f32 %0, %1;" : "=f"(r) : "f"(x)); return r;
}

// Packed constants
#define C2v   0x4B4000004B400000ULL  //  1.5 * 2^23 (round-to-int magic)
#define NEG1v 0xBF800000BF800000ULL  // -1.0f
#define PI2v  0x40C90FDB40C90FDBULL  //  2*pi

// ---------------- prep: fold per-gaussian transcendentals, repack -----------
__global__ void prep_kernel(const float* __restrict__ colors,
                            const float* __restrict__ pos,
                            const float* __restrict__ scales,
                            const float* __restrict__ rots,
                            const float* __restrict__ coeffs,
                            const int*   __restrict__ indices,
                            int G) {
    int g = blockIdx.x * blockDim.x + threadIdx.x;
    if (g >= G) return;
    float s, c;
    sincosf(rots[g], &s, &c);
    float gx = pos[2 * g], gy = pos[2 * g + 1];
    float ox =  gx * c + gy * s;
    float oy = -gx * s + gy * c;
    // s' = e^scale * sqrt(0.5 * log2(e)) :  exp(-0.5*(t e^s)^2) = 2^(-(t s')^2)
    const float SCL = 0.84932180625508979f;
    dP[g] = make_float4(c, -s, s, c);
    dQ[g] = make_float4(-ox, -oy, expf(scales[2 * g]) * SCL,
                                  expf(scales[2 * g + 1]) * SCL);
    dC[g] = make_float4(colors[3 * g], colors[3 * g + 1], colors[3 * g + 2], 0.0f);

    const float FS = 1024.0f / 1024.0f;  // max_frequency / num_frequencies
#pragma unroll
    for (int k = 0; k < 4; k++) {
        float fx = (float)indices[(g * 4 + k) * 2 + 0] * FS;
        float fy = (float)indices[(g * 4 + k) * 2 + 1] * FS;
        float cx = coeffs[(g * 4 + k) * 2 + 0];
        float cy = coeffs[(g * 4 + k) * 2 + 1];
        dFK[g * 4 + k] = make_float4(fx, fy, cx, cy);
    }
}

// ---------------- render: 2 pixels/thread, smem tiles of gaussians ----------
__global__ __launch_bounds__(BLK, 7)
void render_kernel(const float* __restrict__ x, float* __restrict__ out,
                   int N, int G) {
    __shared__ float4 sP [TILE];
    __shared__ float4 sQ [TILE];
    __shared__ float4 sC [TILE];
    __shared__ float4 sFK[TILE * 4];

    int tid  = threadIdx.x;
    int base = blockIdx.x * (2 * BLK);      // 256 pixels per block
    int i0   = base + 2 * tid;              // this thread: pixels i0, i0+1

    float pxa = 0.f, pya = 0.f, pxb = 0.f, pyb = 0.f;
    if (i0 + 1 < N) {
        float4 pp = reinterpret_cast<const float4*>(x)[i0 >> 1];
        pxa = pp.x; pya = pp.y; pxb = pp.z; pyb = pp.w;
    } else if (i0 < N) {
        float2 pp = reinterpret_cast<const float2*>(x)[i0];
        pxa = pp.x; pya = pp.y;
    }
    u64 Pxa = pk2(pxa, pxa), Pya = pk2(pya, pya);
    u64 Pxb = pk2(pxb, pxb), Pyb = pk2(pyb, pyb);

    float a0 = 0.f, a1 = 0.f, a2 = 0.f;
    float b0 = 0.f, b1 = 0.f, b2 = 0.f;

    const ulonglong2* pP  = reinterpret_cast<const ulonglong2*>(sP);
    const ulonglong2* pQ  = reinterpret_cast<const ulonglong2*>(sQ);
    const ulonglong2* pFK = reinterpret_cast<const ulonglong2*>(sFK);

    for (int t0 = 0; t0 < G; t0 += TILE) {
#pragma unroll
        for (int v = tid; v < TILE; v += BLK) {
            int gi = t0 + v;
            if (gi < G) {
                sP[v] = dP[gi];
                sQ[v] = dQ[gi];
                sC[v] = dC[gi];
#pragma unroll
                for (int k = 0; k < 4; k++) sFK[4 * v + k] = dFK[4 * gi + k];
            } else {
                // Zero-fill: identity rotation, zero scales/colors/coeffs ->
                // contribution is exactly 0, keeps inner trip count constant.
                sP[v] = make_float4(1.f, 0.f, 0.f, 1.f);
                sQ[v] = make_float4(0.f, 0.f, 0.f, 0.f);
                sC[v] = make_float4(0.f, 0.f, 0.f, 0.f);
#pragma unroll
                for (int k = 0; k < 4; k++)
                    sFK[4 * v + k] = make_float4(0.f, 0.f, 0.f, 0.f);
            }
        }
        __syncthreads();

#pragma unroll 4
        for (int j = 0; j < TILE; j++) {
            ulonglong2 P = pP[j];            // (c,-s) , (s,c)
            ulonglong2 Q = pQ[j];            // (-ox,-oy) , (sx',sy')

            u64 ta = fma2(Pya, P.y, Q.x);
            ta = fma2(Pxa, P.x, ta);         // (txa, tya)
            u64 tb = fma2(Pyb, P.y, Q.x);
            tb = fma2(Pxb, P.x, tb);         // (txb, tyb)

            u64 ga = mul2(ta, Q.y);
            float gax, gay; upk2(ga, gax, gay);
            float gwa = ex2(fmaf(gax, -gax, gay * -gay));
            u64 gb = mul2(tb, Q.y);
            float gbx, gby; upk2(gb, gbx, gby);
            float gwb = ex2(fmaf(gbx, -gbx, gby * -gby));

            float wxa = 0.f, wya = 0.f, wxb = 0.f, wyb = 0.f;
#pragma unroll
            for (int k = 0; k < 4; k++) {
                ulonglong2 FK = pFK[4 * j + k];   // (fx,fy) , (cx,cy)
                float cx, cy; upk2(FK.y, cx, cy);

                u64 s1a = fma2(ta, FK.x, C2v);    // MAGIC + rint(t*f)  (exact)
                u64 rna = fma2(s1a, NEG1v, C2v);  // -rint(t*f)         (exact)
                u64 da  = fma2(ta, FK.x, rna);    // t*f mod 1, centered
                u64 ara = mul2(da, PI2v);
                float xa0, xa1; upk2(ara, xa0, xa1);
                wxa = fmaf(cosap(xa0), cx, wxa);
                wya = fmaf(cosap(xa1), cy, wya);

                u64 s1b = fma2(tb, FK.x, C2v);
                u64 rnb = fma2(s1b, NEG1v, C2v);
                u64 db  = fma2(tb, FK.x, rnb);
                u64 arb = mul2(db, PI2v);
                float xb0, xb1; upk2(arb, xb0, xb1);
                wxb = fmaf(cosap(xb0), cx, wxb);
                wyb = fmaf(cosap(xb1), cy, wyb);
            }

            float4 C = sC[j];
            float wa = gwa * wxa * wya;
            a0 = fmaf(wa, C.x, a0);
            a1 = fmaf(wa, C.y, a1);
            a2 = fmaf(wa, C.z, a2);
            float wb = gwb * wxb * wyb;
            b0 = fmaf(wb, C.x, b0);
            b1 = fmaf(wb, C.y, b1);
            b2 = fmaf(wb, C.z, b2);
        }
        __syncthreads();
    }

    if (i0 + 1 < N) {
        float2* o2 = reinterpret_cast<float2*>(out + 3 * i0);
        o2[0] = make_float2(a0, a1);
        o2[1] = make_float2(a2, b0);
        o2[2] = make_float2(b1, b2);
    } else if (i0 < N) {
        out[3 * i0 + 0] = a0;
        out[3 * i0 + 1] = a1;
        out[3 * i0 + 2] = a2;
    }
}

// ---------------- harness entry ---------------------------------------------
extern "C" void kernel_launch(void* const* d_in, const int* in_sizes, int n_in,
                              void* d_out, int out_size) {
    const float* x       = (const float*)d_in[0];  // [N,2]
    const float* colors  = (const float*)d_in[1];  // [G,3]
    const float* pos     = (const float*)d_in[2];  // [G,2]
    const float* scales  = (const float*)d_in[3];  // [G,2]
    const float* rots    = (const float*)d_in[4];  // [G,1]
    const float* coeffs  = (const float*)d_in[5];  // [G,4,2]
    const int*   indices = (const int*)  d_in[6];  // [G,4,2]

    int N = in_sizes[0] / 2;
    int G = in_sizes[1] / 3;
    if (G > MAX_G) G = MAX_G;

    (void)cudaFuncSetAttribute(render_kernel,
                               cudaFuncAttributePreferredSharedMemoryCarveout,
                               cudaSharedmemCarveoutMaxShared);

    prep_kernel<<<(G + 255) / 256, 256>>>(colors, pos, scales, rots,
                                          coeffs, indices, G);
    int pixPerBlk = 2 * BLK;
    render_kernel<<<(N + pixPerBlk - 1) / pixPerBlk, BLK>>>(x, (float*)d_out, N, G);
}

// round 17
// speedup vs baseline: 1.5125x; 1.3442x over previous
#include <cuda_runtime.h>

// ----------------------------------------------------------------------------
// PeriodicPrimitives2D — spatial bucket sort of the (random-uniform) pixels
// into a 64x64 grid so warps become spatially coherent, then the proven R11
// render body (2 px/thread, TILE=256, packed-f32x2 exact phase reduction,
// MUFU cos/ex2) with a warp-vote gaussian cull (weight < 2^-17 for the whole
// warp -> skip the 8-cosine series). ~40% of pairs cull at ~12% path cost.
// Counting sort uses atomics; ordering nondeterminism never affects output
// values (each pixel's result depends only on its own coords and is written
// to its original slot).
// ----------------------------------------------------------------------------

#define MAX_G  4096
#define TILE   256
#define BLK    128      // threads per block; each thread owns 2 pixels
#define MAX_N  262144
#define NCELL  4096     // 64 x 64 grid
#define CULL_T (-17.0f) // skip when gaussian weight < 2^-17 for all lanes

typedef unsigned long long u64;

// Per-gaussian packed data (written by prep kernel)
__device__ float4 dP [MAX_G];       // c, -s, s, c
__device__ float4 dQ [MAX_G];       // -ox, -oy, sx', sy'
__device__ float4 dC [MAX_G];       // col0, col1, col2, 0
__device__ float4 dFK[MAX_G * 4];   // fx_k, fy_k, cx_k, cy_k

// Sorting scratch
__device__ int    dHist[NCELL];
__device__ int    dOff [NCELL];
__device__ int    dPerm[MAX_N];     // sorted pos -> original pixel index
__device__ float2 dSX  [MAX_N];     // sorted pixel coords

// ---------------- f32x2 packed helpers --------------------------------------
__device__ __forceinline__ u64 pk2(float a, float b) {
    u64 r;
    asm("mov.b64 %0, {%1, %2};" : "=l"(r)
        : "r"(__float_as_uint(a)), "r"(__float_as_uint(b)));
    return r;
}
__device__ __forceinline__ void upk2(u64 v, float& a, float& b) {
    unsigned int lo, hi;
    asm("mov.b64 {%0, %1}, %2;" : "=r"(lo), "=r"(hi) : "l"(v));
    a = __uint_as_float(lo);
    b = __uint_as_float(hi);
}
__device__ __forceinline__ u64 mul2(u64 a, u64 b) {
    u64 r; asm("mul.rn.f32x2 %0, %1, %2;" : "=l"(r) : "l"(a), "l"(b)); return r;
}
__device__ __forceinline__ u64 fma2(u64 a, u64 b, u64 c) {
    u64 r; asm("fma.rn.f32x2 %0, %1, %2, %3;" : "=l"(r) : "l"(a), "l"(b), "l"(c));
    return r;
}
__device__ __forceinline__ float ex2(float x) {
    float r; asm("ex2.approx.f32 %0, %1;" : "=f"(r) : "f"(x)); return r;
}
__device__ __forceinline__ float cosap(float x) {
    float r; asm("cos.approx.f32 %0, %1;" : "=f"(r) : "f"(x)); return r;
}

// Packed constants
#define C2v   0x4B4000004B400000ULL  //  1.5 * 2^23 (round-to-int magic)
#define NEG1v 0xBF800000BF800000ULL  // -1.0f
#define PI2v  0x40C90FDB40C90FDBULL  //  2*pi

__device__ __forceinline__ int cell_of(float px, float py) {
    int cx = (int)(px * 64.0f); cx = max(0, min(63, cx));
    int cy = (int)(py * 64.0f); cy = max(0, min(63, cy));
    return cy * 64 + cx;
}

// ---------------- sorting kernels -------------------------------------------
__global__ void zero_kernel() {
    int i = blockIdx.x * blockDim.x + threadIdx.x;
    if (i < NCELL) dHist[i] = 0;
}

__global__ void hist_kernel(const float* __restrict__ x, int N) {
    int i = blockIdx.x * blockDim.x + threadIdx.x;
    if (i >= N) return;
    float2 p = reinterpret_cast<const float2*>(x)[i];
    atomicAdd(&dHist[cell_of(p.x, p.y)], 1);
}

__global__ void scan_kernel() {   // 1 block, 1024 threads, 4 cells each
    __shared__ int part[1024];
    int tid = threadIdx.x;
    int v[4], s = 0;
#pragma unroll
    for (int q = 0; q < 4; q++) { v[q] = dHist[tid * 4 + q]; s += v[q]; }
    part[tid] = s;
    __syncthreads();
    for (int off = 1; off < 1024; off <<= 1) {
        int t = (tid >= off) ? part[tid - off] : 0;
        __syncthreads();
        part[tid] += t;
        __syncthreads();
    }
    int excl = (tid == 0) ? 0 : part[tid - 1];
#pragma unroll
    for (int q = 0; q < 4; q++) { dOff[tid * 4 + q] = excl; excl += v[q]; }
}

__global__ void scatter_kernel(const float* __restrict__ x, int N) {
    int i = blockIdx.x * blockDim.x + threadIdx.x;
    if (i >= N) return;
    float2 p = reinterpret_cast<const float2*>(x)[i];
    int c = cell_of(p.x, p.y);
    int pos = atomicAdd(&dOff[c], 1);
    dPerm[pos] = i;
    dSX[pos] = p;
}

// ---------------- prep: fold per-gaussian transcendentals, repack -----------
__global__ void prep_kernel(const float* __restrict__ colors,
                            const float* __restrict__ pos,
                            const float* __restrict__ scales,
                            const float* __restrict__ rots,
                            const float* __restrict__ coeffs,
                            const int*   __restrict__ indices,
                            int G) {
    int g = blockIdx.x * blockDim.x + threadIdx.x;
    if (g >= G) return;
    float s, c;
    sincosf(rots[g], &s, &c);
    float gx = pos[2 * g], gy = pos[2 * g + 1];
    float ox =  gx * c + gy * s;
    float oy = -gx * s + gy * c;
    // s' = e^scale * sqrt(0.5 * log2(e)) :  exp(-0.5*(t e^s)^2) = 2^(-(t s')^2)
    const float SCL = 0.84932180625508979f;
    dP[g] = make_float4(c, -s, s, c);
    dQ[g] = make_float4(-ox, -oy, expf(scales[2 * g]) * SCL,
                                  expf(scales[2 * g + 1]) * SCL);
    dC[g] = make_float4(colors[3 * g], colors[3 * g + 1], colors[3 * g + 2], 0.0f);

    const float FS = 1024.0f / 1024.0f;  // max_frequency / num_frequencies
#pragma unroll
    for (int k = 0; k < 4; k++) {
        float fx = (float)indices[(g * 4 + k) * 2 + 0] * FS;
        float fy = (float)indices[(g * 4 + k) * 2 + 1] * FS;
        float cx = coeffs[(g * 4 + k) * 2 + 0];
        float cy = coeffs[(g * 4 + k) * 2 + 1];
        dFK[g * 4 + k] = make_float4(fx, fy, cx, cy);
    }
}

// ---------------- render: sorted pixels, 2 px/thread, warp-vote cull --------
__global__ __launch_bounds__(BLK, 7)
void render_kernel(float* __restrict__ out, int N, int G) {
    __shared__ float4 sP [TILE];
    __shared__ float4 sQ [TILE];
    __shared__ float4 sC [TILE];
    __shared__ float4 sFK[TILE * 4];

    int tid  = threadIdx.x;
    int base = blockIdx.x * (2 * BLK);      // 256 sorted pixels per block
    int s0   = base + 2 * tid;              // sorted positions s0, s0+1

    float pxa = 0.f, pya = 0.f, pxb = 0.f, pyb = 0.f;
    int oa = 0, ob = 0;
    bool va = (s0 < N), vb = (s0 + 1 < N);
    if (va) { float2 p = dSX[s0];     pxa = p.x; pya = p.y; oa = dPerm[s0]; }
    if (vb) { float2 p = dSX[s0 + 1]; pxb = p.x; pyb = p.y; ob = dPerm[s0 + 1]; }

    u64 Pxa = pk2(pxa, pxa), Pya = pk2(pya, pya);
    u64 Pxb = pk2(pxb, pxb), Pyb = pk2(pyb, pyb);

    float a0 = 0.f, a1 = 0.f, a2 = 0.f;
    float b0 = 0.f, b1 = 0.f, b2 = 0.f;

    const ulonglong2* pP  = reinterpret_cast<const ulonglong2*>(sP);
    const ulonglong2* pQ  = reinterpret_cast<const ulonglong2*>(sQ);
    const ulonglong2* pFK = reinterpret_cast<const ulonglong2*>(sFK);

    for (int t0 = 0; t0 < G; t0 += TILE) {
#pragma unroll
        for (int v = tid; v < TILE; v += BLK) {
            int gi = t0 + v;
            if (gi < G) {
                sP[v] = dP[gi];
                sQ[v] = dQ[gi];
                sC[v] = dC[gi];
#pragma unroll
                for (int k = 0; k < 4; k++) sFK[4 * v + k] = dFK[4 * gi + k];
            }
        }
        __syncthreads();

        int cnt = min(TILE, G - t0);
#pragma unroll 1
        for (int j = 0; j < cnt; j++) {
            ulonglong2 P = pP[j];            // (c,-s) , (s,c)
            ulonglong2 Q = pQ[j];            // (-ox,-oy) , (sx',sy')

            u64 ta = fma2(Pya, P.y, Q.x);
            ta = fma2(Pxa, P.x, ta);         // (txa, tya)
            u64 tb = fma2(Pyb, P.y, Q.x);
            tb = fma2(Pxb, P.x, tb);         // (txb, tyb)

            u64 ga = mul2(ta, Q.y);
            float gax, gay; upk2(ga, gax, gay);
            float sqa = fmaf(gax, -gax, gay * -gay);
            u64 gb = mul2(tb, Q.y);
            float gbx, gby; upk2(gb, gbx, gby);
            float sqb = fmaf(gbx, -gbx, gby * -gby);

            // Warp-coherent cull (pixels spatially sorted -> coherent vote)
            if (__all_sync(0xffffffffu, fmaxf(sqa, sqb) < CULL_T)) continue;

            float gwa = ex2(sqa);
            float gwb = ex2(sqb);

            float wxa = 0.f, wya = 0.f, wxb = 0.f, wyb = 0.f;
#pragma unroll
            for (int k = 0; k < 4; k++) {
                ulonglong2 FK = pFK[4 * j + k];   // (fx,fy) , (cx,cy)
                float cx, cy; upk2(FK.y, cx, cy);

                u64 s1a = fma2(ta, FK.x, C2v);    // MAGIC + rint(t*f)  (exact)
                u64 rna = fma2(s1a, NEG1v, C2v);  // -rint(t*f)         (exact)
                u64 da  = fma2(ta, FK.x, rna);    // t*f mod 1, centered
                u64 ara = mul2(da, PI2v);
                float xa0, xa1; upk2(ara, xa0, xa1);
                wxa = fmaf(cosap(xa0), cx, wxa);
                wya = fmaf(cosap(xa1), cy, wya);

                u64 s1b = fma2(tb, FK.x, C2v);
                u64 rnb = fma2(s1b, NEG1v, C2v);
                u64 db  = fma2(tb, FK.x, rnb);
                u64 arb = mul2(db, PI2v);
                float xb0, xb1; upk2(arb, xb0, xb1);
                wxb = fmaf(cosap(xb0), cx, wxb);
                wyb = fmaf(cosap(xb1), cy, wyb);
            }

            float4 C = sC[j];
            float wa = gwa * wxa * wya;
            a0 = fmaf(wa, C.x, a0);
            a1 = fmaf(wa, C.y, a1);
            a2 = fmaf(wa, C.z, a2);
            float wb = gwb * wxb * wyb;
            b0 = fmaf(wb, C.x, b0);
            b1 = fmaf(wb, C.y, b1);
            b2 = fmaf(wb, C.z, b2);
        }
        __syncthreads();
    }

    if (va) {
        out[3 * oa + 0] = a0;
        out[3 * oa + 1] = a1;
        out[3 * oa + 2] = a2;
    }
    if (vb) {
        out[3 * ob + 0] = b0;
        out[3 * ob + 1] = b1;
        out[3 * ob + 2] = b2;
    }
}

// ---------------- harness entry ---------------------------------------------
extern "C" void kernel_launch(void* const* d_in, const int* in_sizes, int n_in,
                              void* d_out, int out_size) {
    const float* x       = (const float*)d_in[0];  // [N,2]
    const float* colors  = (const float*)d_in[1];  // [G,3]
    const float* pos     = (const float*)d_in[2];  // [G,2]
    const float* scales  = (const float*)d_in[3];  // [G,2]
    const float* rots    = (const float*)d_in[4];  // [G,1]
    const float* coeffs  = (const float*)d_in[5];  // [G,4,2]
    const int*   indices = (const int*)  d_in[6];  // [G,4,2]

    int N = in_sizes[0] / 2;
    int G = in_sizes[1] / 3;
    if (G > MAX_G) G = MAX_G;
    if (N > MAX_N) N = MAX_N;

    (void)cudaFuncSetAttribute(render_kernel,
                               cudaFuncAttributePreferredSharedMemoryCarveout,
                               cudaSharedmemCarveoutMaxShared);

    prep_kernel<<<(G + 255) / 256, 256>>>(colors, pos, scales, rots,
                                          coeffs, indices, G);

    // Spatial counting sort of pixels (atomic order never affects out values)
    zero_kernel<<<(NCELL + 255) / 256, 256>>>();
    hist_kernel<<<(N + 255) / 256, 256>>>(x, N);
    scan_kernel<<<1, 1024>>>();
    scatter_kernel<<<(N + 255) / 256, 256>>>(x, N);

    int pixPerBlk = 2 * BLK;
    render_kernel<<<(N + pixPerBlk - 1) / pixPerBlk, BLK>>>((float*)d_out, N, G);
}